// round 7
// baseline (speedup 1.0000x reference)
#include <cuda_runtime.h>
#include <math_constants.h>
#include <cstdint>

#define BM     128
#define NT     512
#define KDIM   2048
#define NEXP   64
#define BK     32
#define NKT    (KDIM / BK)           // 64
#define STAGES 3
#define A_STRIDE 36                   // 32 + 4 pad floats (16B-aligned rows)
#define STAGE_A  (BM * A_STRIDE)      // 4608 floats
#define STAGE_B  (BK * 128)           // 4096 floats
#define STAGE_F  (STAGE_A + STAGE_B)  // 8704 floats
#define SMEM_BYTES (STAGES * STAGE_F * 4)   // 104448 B

typedef unsigned long long ull;

__device__ __forceinline__ ull pack2(float lo, float hi) {
    ull r;
    asm("mov.b64 %0, {%1, %2};" : "=l"(r) : "f"(lo), "f"(hi));
    return r;
}
__device__ __forceinline__ void unpack2(ull v, float& lo, float& hi) {
    asm("mov.b64 {%0, %1}, %2;" : "=f"(lo), "=f"(hi) : "l"(v));
}
// Packed dual-FP32 FMA (sm_100+): d = a * b + d on two lanes at once.
__device__ __forceinline__ void ffma2(ull& d, ull a, ull b) {
    asm("fma.rn.f32x2 %0, %1, %2, %0;" : "+l"(d) : "l"(a), "l"(b));
}
__device__ __forceinline__ void cp16(float* s, const float* g) {
    unsigned sa = (unsigned)__cvta_generic_to_shared(s);
    asm volatile("cp.async.cg.shared.global [%0], [%1], 16;" :: "r"(sa), "l"(g));
}
__device__ __forceinline__ void cp_commit() {
    asm volatile("cp.async.commit_group;");
}
__device__ __forceinline__ void cp_wait1() {
    asm volatile("cp.async.wait_group 1;");
}

__global__ void __launch_bounds__(NT, 2)
routing_kernel(const float* __restrict__ x,
               const float* __restrict__ wg,
               const float* __restrict__ wn,
               const float* __restrict__ noise,
               float* __restrict__ out)
{
    extern __shared__ __align__(16) float smem[];

    const int tid = threadIdx.x;
    const int tx  = tid & 15;    // col group: gate cols [4tx,4tx+4), noise cols [64+4tx,...)
    const int ty  = tid >> 4;    // row group 0..31: rows [4ty, 4ty+4)
    const int m0  = blockIdx.x * BM;

    // ---- zero this block's out slice (harness poisons d_out) ----
    {
        float4 z = make_float4(0.f, 0.f, 0.f, 0.f);
        float4* ob = reinterpret_cast<float4*>(out + (size_t)m0 * NEXP);
        #pragma unroll
        for (int i = 0; i < (BM * NEXP / 4) / NT; ++i)
            ob[tid + i * NT] = z;
    }

    // ---- staging index precompute ----
    // A: 128 rows x 32 k per stage = 1024 float4; thread -> row tid>>2, k-off 8*(tid&3), +4
    const int rowA  = tid >> 2;          // 0..127
    const int koffA = (tid & 3) * 8;     // 0,8,16,24
    // B: 32 k-rows x 128 cols = 1024 float4; thread -> k-row tid>>4, cols 8*(tid&15), +4
    const int kB = tid >> 4;             // 0..31
    const int cB = (tid & 15) * 8;       // 0..120, 8-col chunks never straddle col 64

    const float* gA   = x + (size_t)(m0 + rowA) * KDIM + koffA;
    const float* wsrc = (cB < NEXP) ? (wg + cB) : (wn + (cB - NEXP));

    // acc[m][cp]: packed pair (col 4tx+2cp, 4tx+2cp+1) for row 4ty+m.
    // cp 0,1 = gate cols; cp 2,3 = noise cols (B cols 64+4tx..)
    ull acc[4][4];
    #pragma unroll
    for (int m = 0; m < 4; ++m)
        #pragma unroll
        for (int c = 0; c < 4; ++c) acc[m][c] = 0ull;

    // ---- prologue: stage chunks 0,1 ----
    #pragma unroll
    for (int s = 0; s < STAGES - 1; ++s) {
        float* st = smem + s * STAGE_F;
        const float* ga = gA + s * BK;
        cp16(st + rowA * A_STRIDE + koffA,     ga);
        cp16(st + rowA * A_STRIDE + koffA + 4, ga + 4);
        const float* gb = wsrc + (size_t)(s * BK + kB) * NEXP;
        float* sb = st + STAGE_A + kB * 128 + cB;
        cp16(sb,     gb);
        cp16(sb + 4, gb + 4);
        cp_commit();
    }

    // ---- main loop: 3-stage cp.async pipeline, 1 sync per 32-K chunk ----
    int cbuf = 0;   // compute buffer for chunk kt
    int wbuf = 2;   // write buffer for chunk kt+2  ( == (cbuf+2)%3 )
    for (int kt = 0; kt < NKT; ++kt) {
        cp_wait1();           // group for chunk kt complete (<=1 younger pending)
        __syncthreads();      // all warps done computing the buffer we overwrite below

        const int nx = kt + STAGES - 1;
        if (nx < NKT) {
            float* st = smem + wbuf * STAGE_F;
            const float* ga = gA + nx * BK;
            cp16(st + rowA * A_STRIDE + koffA,     ga);
            cp16(st + rowA * A_STRIDE + koffA + 4, ga + 4);
            const float* gb = wsrc + (size_t)(nx * BK + kB) * NEXP;
            float* sb = st + STAGE_A + kB * 128 + cB;
            cp16(sb,     gb);
            cp16(sb + 4, gb + 4);
        }
        cp_commit();          // commit every iter (possibly empty) -> uniform group counting

        const float* st = smem + cbuf * STAGE_F;
        const float* Ab = st + (ty * 4) * A_STRIDE;   // 4 rows, stride 36
        const float* Bb = st + STAGE_A + tx * 4;      // cols 4tx (gate), 64+4tx (noise)

        #pragma unroll
        for (int kk = 0; kk < BK; ++kk) {
            // B pairs packed straight from smem (two-phase conflict-free LDS.128)
            ulonglong2 b01 = *reinterpret_cast<const ulonglong2*>(Bb + kk * 128);
            ulonglong2 b23 = *reinterpret_cast<const ulonglong2*>(Bb + kk * 128 + 64);
            #pragma unroll
            for (int m = 0; m < 4; ++m) {
                float a = Ab[m * A_STRIDE + kk];      // warp-broadcast scalar LDS
                ull aa = pack2(a, a);
                ffma2(acc[m][0], aa, b01.x);
                ffma2(acc[m][1], aa, b01.y);
                ffma2(acc[m][2], aa, b23.x);
                ffma2(acc[m][3], aa, b23.y);
            }
        }

        if (++cbuf == STAGES) cbuf = 0;
        if (++wbuf == STAGES) wbuf = 0;
    }

    // ---- epilogue: gate & matching noise cols live in the SAME thread ----
    const unsigned FULL = 0xffffffffu;

    #pragma unroll
    for (int m = 0; m < 4; ++m) {
        const int grow = m0 + ty * 4 + m;

        float g[4], w[4];
        unpack2(acc[m][0], g[0], g[1]);
        unpack2(acc[m][1], g[2], g[3]);
        unpack2(acc[m][2], w[0], w[1]);
        unpack2(acc[m][3], w[2], w[3]);

        float4 nn = *reinterpret_cast<const float4*>(noise + (size_t)grow * NEXP + tx * 4);
        float nv[4] = {nn.x, nn.y, nn.z, nn.w};

        // local top-2 over 4 experts (ascending index + strict '>' => lowest-index tie-break)
        float v1 = -CUDART_INF_F, v2 = -CUDART_INF_F;
        int   i1 = 1 << 20,       i2 = 1 << 20;
        #pragma unroll
        for (int c = 0; c < 4; ++c) {
            float t  = w[c];
            float sp = fmaxf(t, 0.f) + log1pf(expf(-fabsf(t))) + 0.01f;  // softplus+eps
            float val = g[c] + nv[c] * sp;
            int   e   = tx * 4 + c;
            if (val > v1)      { v2 = v1; i2 = i1; v1 = val; i1 = e; }
            else if (val > v2) { v2 = val; i2 = e; }
        }

        // butterfly merge across the 16 tx lanes (xor 1,2,4,8 stays in the half-warp)
        #pragma unroll
        for (int d = 1; d < 16; d <<= 1) {
            float ov1 = __shfl_xor_sync(FULL, v1, d);
            int   oi1 = __shfl_xor_sync(FULL, i1, d);
            float ov2 = __shfl_xor_sync(FULL, v2, d);
            int   oi2 = __shfl_xor_sync(FULL, i2, d);
            bool ofirst = (ov1 > v1) || (ov1 == v1 && oi1 < i1);
            if (ofirst) {
                bool mine2 = (v1 > ov2) || (v1 == ov2 && i1 < oi2);
                v2 = mine2 ? v1 : ov2;
                i2 = mine2 ? i1 : oi2;
                v1 = ov1;  i1 = oi1;
            } else {
                bool osec = (ov1 > v2) || (ov1 == v2 && oi1 < i2);
                if (osec) { v2 = ov1; i2 = oi1; }
            }
        }

        // 2-way softmax (v1 >= v2) and scatter
        if (tx == 0) {
            float ex = expf(v2 - v1);
            float g1 = 1.f / (1.f + ex);
            out[(size_t)grow * NEXP + i1] = g1;
            out[(size_t)grow * NEXP + i2] = ex * g1;
        }
    }
}

extern "C" void kernel_launch(void* const* d_in, const int* in_sizes, int n_in,
                              void* d_out, int out_size)
{
    (void)in_sizes; (void)n_in; (void)out_size;
    const float* x  = (const float*)d_in[0];
    const float* wg = (const float*)d_in[1];
    const float* wn = (const float*)d_in[2];
    const float* nz = (const float*)d_in[3];
    float* out = (float*)d_out;

    cudaFuncSetAttribute(routing_kernel,
                         cudaFuncAttributeMaxDynamicSharedMemorySize, SMEM_BYTES);
    routing_kernel<<<32768 / BM, NT, SMEM_BYTES>>>(x, wg, wn, nz, out);
}